// round 15
// baseline (speedup 1.0000x reference)
#include <cuda_runtime.h>
#include <cuda_bf16.h>
#include <cuda_fp16.h>
#include <math.h>
#include <stdint.h>

// Problem constants
#define BB   2
#define SS   1024
#define PP   1024
#define TT   (PP + SS)
#define HH   4096
#define NQ   32
#define NKV  8
#define DD   128
#define QKVN ((NQ + 2 * NKV) * DD)   // 6144
#define SCALE 0.08838834764831845f   // 1/sqrt(128)

// ---------------------------------------------------------------------------
// Scratch (device globals: no allocation allowed)
// ---------------------------------------------------------------------------
__device__ __half g_hid[BB * SS * HH];
__device__ __half g_wqkv[(size_t)QKVN * HH];         // transposed [N,K]
__device__ __half g_wo[(size_t)HH * HH];             // transposed [N,K]
__device__ __half g_attn_h[BB * SS * NQ * DD];
__device__ __half g_attn_l[BB * SS * NQ * DD];
__device__ __half g_q_f[(size_t)BB * NQ * SS * DD];
__device__ __half g_k_f[(size_t)BB * NKV * TT * DD];
__device__ __half g_v_f[(size_t)BB * NKV * TT * DD];

// ---------------------------------------------------------------------------
// Low-level helpers (plain sm_80+ ISA)
// ---------------------------------------------------------------------------
__device__ __forceinline__ uint32_t smem_u32(const void* p) {
    uint32_t a;
    asm("{ .reg .u64 t; cvta.to.shared.u64 t, %1; cvt.u32.u64 %0, t; }"
        : "=r"(a) : "l"(p));
    return a;
}
__device__ __forceinline__ void cp16(uint32_t dst, const void* src) {
    asm volatile("cp.async.cg.shared.global [%0], [%1], 16;"
                 :: "r"(dst), "l"(src));
}
__device__ __forceinline__ void ldsm4(uint32_t* r, uint32_t a) {
    asm volatile("ldmatrix.sync.aligned.m8n8.x4.shared.b16 {%0,%1,%2,%3}, [%4];"
                 : "=r"(r[0]), "=r"(r[1]), "=r"(r[2]), "=r"(r[3]) : "r"(a));
}
__device__ __forceinline__ void ldsm4t(uint32_t* r, uint32_t a) {
    asm volatile("ldmatrix.sync.aligned.m8n8.x4.trans.shared.b16 {%0,%1,%2,%3}, [%4];"
                 : "=r"(r[0]), "=r"(r[1]), "=r"(r[2]), "=r"(r[3]) : "r"(a));
}
__device__ __forceinline__ void mma16816h(float* c, const uint32_t* a,
                                          const uint32_t b0, const uint32_t b1) {
    asm volatile(
        "mma.sync.aligned.m16n8k16.row.col.f32.f16.f16.f32 "
        "{%0,%1,%2,%3}, {%4,%5,%6,%7}, {%8,%9}, {%0,%1,%2,%3};"
        : "+f"(c[0]), "+f"(c[1]), "+f"(c[2]), "+f"(c[3])
        : "r"(a[0]), "r"(a[1]), "r"(a[2]), "r"(a[3]), "r"(b0), "r"(b1));
}

// ---------------------------------------------------------------------------
// fp32 -> fp16 convert (GEMM1 activations)
// ---------------------------------------------------------------------------
__global__ void conv_f16(const float* __restrict__ x,
                         __half* __restrict__ xo, int n)
{
    int i = blockIdx.x * blockDim.x + threadIdx.x;
    if (i >= n) return;
    xo[i] = __float2half(x[i]);
}

// fp32 [R,C] -> fp16 transposed [C,R] (weights)
__global__ void trans_f16(const float* __restrict__ x,
                          __half* __restrict__ xo, int R, int C)
{
    __shared__ float t[32][33];
    int r0 = blockIdx.y * 32, c0 = blockIdx.x * 32;
    int tx = threadIdx.x, ty = threadIdx.y;
#pragma unroll
    for (int j = 0; j < 4; j++)
        t[ty + 8 * j][tx] = x[(size_t)(r0 + ty + 8 * j) * C + c0 + tx];
    __syncthreads();
#pragma unroll
    for (int j = 0; j < 4; j++)
        xo[(size_t)(c0 + ty + 8 * j) * R + r0 + tx] = __float2half(t[tx][ty + 8 * j]);
}

// ---------------------------------------------------------------------------
// KV-cache conversion only (new-token K/V now written by GEMM1's epilogue).
// ---------------------------------------------------------------------------
#define CACHETOT (BB * NKV * PP * 64)

__global__ void conv_cache_f16(const float* __restrict__ kcache,
                               const float* __restrict__ vcache,
                               __half* __restrict__ kf, __half* __restrict__ vf)
{
    int idx = blockIdx.x * blockDim.x + threadIdx.x;
    if (idx >= CACHETOT) return;
    int d = idx & 63;
    int rest = idx >> 6;
    int t = rest % PP;
    int kh = (rest / PP) % NKV;
    int b = rest / (PP * NKV);
    size_t src = (((size_t)(b * PP + t)) * NKV + kh) * DD;
    size_t o = (((size_t)(b * NKV + kh)) * TT + t) * DD + d;
    kf[o]      = __float2half(kcache[src + d]);
    kf[o + 64] = __float2half(kcache[src + d + 64]);
    vf[o]      = __float2half(vcache[src + d]);
    vf[o + 64] = __float2half(vcache[src + d + 64]);
}

// ---------------------------------------------------------------------------
// Fused QKV GEMM: 128x256x64, 8 warps, 3-stage pipeline, reg double-buffered
// fragments (round-12 mainloop). Epilogue stages the fp32 tile in smem, then
// applies RoPE (+scale for Q) and writes fp16 directly to q/k/v layouts.
// Each block tile (256 cols) is entirely Q, K, or V.
// ---------------------------------------------------------------------------
#define X1_A_OFF 0
#define X1_B_OFF 16384
#define X1_STAGE 49152
#define GEMM1_SMEM (3 * X1_STAGE)   // 147456 (epilogue needs 128*257*4 = 131584)

#define LOAD_STAGE1(c, s) do {                                             \
    int _k0 = (c) * 64;                                                    \
    uint32_t _stb = smb + (s) * X1_STAGE;                                  \
    _Pragma("unroll")                                                      \
    for (int _i = 0; _i < 4; _i++) {                                       \
        int _id = tid + _i * 256;                                          \
        int _row = _id >> 3, _ch = _id & 7;                                \
        uint32_t _sw = (_row << 7) + ((_ch ^ (_row & 7)) << 4);            \
        cp16(_stb + X1_A_OFF + _sw, srcA + (size_t)_row * K + _k0 + _ch * 8); \
    }                                                                      \
    _Pragma("unroll")                                                      \
    for (int _i = 0; _i < 8; _i++) {                                       \
        int _id = tid + _i * 256;                                          \
        int _row = _id >> 3, _ch = _id & 7;                                \
        uint32_t _sw = (_row << 7) + ((_ch ^ (_row & 7)) << 4);            \
        cp16(_stb + X1_B_OFF + _sw, srcB + (size_t)_row * K + _k0 + _ch * 8); \
    }                                                                      \
    asm volatile("cp.async.commit_group;");                                \
} while (0)

__global__ __launch_bounds__(256, 1) void gemm_qkv_fused(
    const __half* __restrict__ A, const __half* __restrict__ B,
    const float* __restrict__ cosb, const float* __restrict__ sinb,
    __half* __restrict__ qf, __half* __restrict__ kf, __half* __restrict__ vf,
    int M, int N, int K)
{
    extern __shared__ char sm[];
    const uint32_t smb = smem_u32(sm);
    const int tid = threadIdx.x;
    const int wid = tid >> 5, lane = tid & 31;
    const int bm = blockIdx.y * 128, bn = blockIdx.x * 256;
    const int wm = (wid & 1) * 64, wn = (wid >> 1) * 64;

    const __half* srcA = A + (size_t)bm * K;
    const __half* srcB = B + (size_t)bn * K;

    uint32_t arb[4], brb[4];
    int rswA[4], rswB[4];
#pragma unroll
    for (int mi = 0; mi < 4; mi++) {
        int row = wm + mi * 16 + (lane & 15);
        arb[mi] = (uint32_t)(row << 7) + X1_A_OFF;
        rswA[mi] = row & 7;
    }
#pragma unroll
    for (int ni = 0; ni < 4; ni++) {
        int row = wn + ni * 16 + (lane & 15);
        brb[ni] = (uint32_t)(row << 7) + X1_B_OFF;
        rswB[ni] = row & 7;
    }

    float acc[4][8][4];
#pragma unroll
    for (int i = 0; i < 4; i++)
#pragma unroll
        for (int j = 0; j < 8; j++)
#pragma unroll
            for (int e = 0; e < 4; e++) acc[i][j][e] = 0.f;

    const int NC = K / 64;
    LOAD_STAGE1(0, 0);
    LOAD_STAGE1(1, 1);

    uint32_t ah[2][4][4], bh[2][4][4];
    int sc = 0, sl = 2;
    for (int c = 0; c < NC; c++) {
        __syncthreads();
        if (c + 2 < NC) {
            LOAD_STAGE1(c + 2, sl);
            asm volatile("cp.async.wait_group 2;");
        } else if (c + 1 < NC) {
            asm volatile("cp.async.wait_group 1;");
        } else {
            asm volatile("cp.async.wait_group 0;");
        }
        __syncthreads();

        const uint32_t base = smb + sc * X1_STAGE;
        {
            const int c0 = (lane >> 4);
#pragma unroll
            for (int mi = 0; mi < 4; mi++)
                ldsm4(ah[0][mi], base + arb[mi] + ((c0 ^ rswA[mi]) << 4));
#pragma unroll
            for (int ni = 0; ni < 4; ni++)
                ldsm4(bh[0][ni], base + brb[ni] + ((c0 ^ rswB[ni]) << 4));
        }
#pragma unroll
        for (int ks = 0; ks < 4; ks++) {
            const int cur = ks & 1, nxt = cur ^ 1;
            if (ks < 3) {
                const int c0 = (ks + 1) * 2 + (lane >> 4);
#pragma unroll
                for (int mi = 0; mi < 4; mi++)
                    ldsm4(ah[nxt][mi], base + arb[mi] + ((c0 ^ rswA[mi]) << 4));
#pragma unroll
                for (int ni = 0; ni < 4; ni++)
                    ldsm4(bh[nxt][ni], base + brb[ni] + ((c0 ^ rswB[ni]) << 4));
            }
#pragma unroll
            for (int mi = 0; mi < 4; mi++)
#pragma unroll
                for (int ni = 0; ni < 4; ni++)
#pragma unroll
                    for (int sel = 0; sel < 2; sel++)
                        mma16816h(acc[mi][ni * 2 + sel], ah[cur][mi],
                                  bh[cur][ni][sel], bh[cur][ni][sel + 2]);
        }
        sc = (sc == 2) ? 0 : sc + 1;
        sl = (sl == 2) ? 0 : sl + 1;
    }

    // --- fused epilogue: stage fp32 tile in smem, RoPE + fp16 scatter ---
    __syncthreads();
    float* so = (float*)sm;
    const int g = lane >> 2, t = lane & 3;
#pragma unroll
    for (int mi = 0; mi < 4; mi++) {
#pragma unroll
        for (int nj = 0; nj < 8; nj++) {
            const float* a = acc[mi][nj];
            int row = wm + mi * 16 + g;
            int col = wn + nj * 8 + t * 2;
            so[row * 257 + col]           = a[0];
            so[row * 257 + col + 1]       = a[1];
            so[(row + 8) * 257 + col]     = a[2];
            so[(row + 8) * 257 + col + 1] = a[3];
        }
    }
    __syncthreads();

    const int btype = (bn < NQ * DD) ? 0 : ((bn < (NQ + NKV) * DD) ? 1 : 2);
    for (int i = tid; i < 128 * 128; i += 256) {
        int row = i >> 7, p = i & 127;
        int hh = p >> 6, d = p & 63;
        int col1 = hh * 128 + d;
        float x1 = so[row * 257 + col1];
        float x2 = so[row * 257 + col1 + 64];
        int grow = bm + row;
        int b = grow >> 10, s = grow & (SS - 1);
        int gcol = bn + col1;
        if (btype == 0) {
            float c0 = cosb[s * DD + d],      s0 = sinb[s * DD + d];
            float c1 = cosb[s * DD + d + 64], s1 = sinb[s * DD + d + 64];
            float y1 = (x1 * c0 - x2 * s0) * SCALE;
            float y2 = (x2 * c1 + x1 * s1) * SCALE;
            int hq = gcol >> 7;
            size_t o = (((size_t)(b * NQ + hq)) * SS + s) * DD + d;
            qf[o]      = __float2half(y1);
            qf[o + 64] = __float2half(y2);
        } else if (btype == 1) {
            float c0 = cosb[s * DD + d],      s0 = sinb[s * DD + d];
            float c1 = cosb[s * DD + d + 64], s1 = sinb[s * DD + d + 64];
            float y1 = x1 * c0 - x2 * s0;
            float y2 = x2 * c1 + x1 * s1;
            int kh = (gcol - NQ * DD) >> 7;
            size_t o = (((size_t)(b * NKV + kh)) * TT + PP + s) * DD + d;
            kf[o]      = __float2half(y1);
            kf[o + 64] = __float2half(y2);
        } else {
            int vh = (gcol - (NQ + NKV) * DD) >> 7;
            size_t o = (((size_t)(b * NKV + vh)) * TT + PP + s) * DD + d;
            vf[o]      = __float2half(x1);
            vf[o + 64] = __float2half(x2);
        }
    }
}

// ---------------------------------------------------------------------------
// fp16x2 GEMM (output projection) — round-12 version, unchanged.
// ---------------------------------------------------------------------------
#define AH_OFF 0
#define AL_OFF 16384
#define BH_OFF 32768
#define STAGE_B  65536
#define GEMM_SMEM (3 * STAGE_B)

#define LOAD_STAGE(c, s) do {                                              \
    int _k0 = (c) * 64;                                                    \
    uint32_t _stb = smb + (s) * STAGE_B;                                   \
    _Pragma("unroll")                                                      \
    for (int _i = 0; _i < 4; _i++) {                                       \
        int _id = tid + _i * 256;                                          \
        int _row = _id >> 3, _ch = _id & 7;                                \
        uint32_t _sw = (_row << 7) + ((_ch ^ (_row & 7)) << 4);            \
        const size_t _go = (size_t)_row * K + _k0 + _ch * 8;               \
        cp16(_stb + AH_OFF + _sw, srcAh + _go);                            \
        cp16(_stb + AL_OFF + _sw, srcAl + _go);                            \
    }                                                                      \
    _Pragma("unroll")                                                      \
    for (int _i = 0; _i < 8; _i++) {                                       \
        int _id = tid + _i * 256;                                          \
        int _row = _id >> 3, _ch = _id & 7;                                \
        uint32_t _sw = (_row << 7) + ((_ch ^ (_row & 7)) << 4);            \
        cp16(_stb + BH_OFF + _sw, srcB + (size_t)_row * K + _k0 + _ch * 8); \
    }                                                                      \
    asm volatile("cp.async.commit_group;");                                \
} while (0)

__global__ __launch_bounds__(256, 1) void gemm_f16x2(
    const __half* __restrict__ Ah, const __half* __restrict__ Al,
    const __half* __restrict__ B,
    float* __restrict__ C, int M, int N, int K)
{
    extern __shared__ char sm[];
    const uint32_t smb = smem_u32(sm);
    const int tid = threadIdx.x;
    const int wid = tid >> 5, lane = tid & 31;
    const int bm = blockIdx.y * 128, bn = blockIdx.x * 256;
    const int wm = (wid & 1) * 64, wn = (wid >> 1) * 64;

    const __half* srcAh = Ah + (size_t)bm * K;
    const __half* srcAl = Al + (size_t)bm * K;
    const __half* srcB  = B  + (size_t)bn * K;

    uint32_t arb[4], brb[4];
    int rswA[4], rswB[4];
#pragma unroll
    for (int mi = 0; mi < 4; mi++) {
        int row = wm + mi * 16 + (lane & 15);
        arb[mi] = (uint32_t)(row << 7);
        rswA[mi] = row & 7;
    }
#pragma unroll
    for (int ni = 0; ni < 4; ni++) {
        int row = wn + ni * 16 + (lane & 15);
        brb[ni] = (uint32_t)(row << 7);
        rswB[ni] = row & 7;
    }

    float acc[4][8][4];
#pragma unroll
    for (int i = 0; i < 4; i++)
#pragma unroll
        for (int j = 0; j < 8; j++)
#pragma unroll
            for (int e = 0; e < 4; e++) acc[i][j][e] = 0.f;

    const int NC = K / 64;
    LOAD_STAGE(0, 0);
    LOAD_STAGE(1, 1);

    uint32_t ah[2][4][4], bh[2][4][4], al[4][4];
    int sc = 0, sl = 2;
    for (int c = 0; c < NC; c++) {
        __syncthreads();
        if (c + 2 < NC) {
            LOAD_STAGE(c + 2, sl);
            asm volatile("cp.async.wait_group 2;");
        } else if (c + 1 < NC) {
            asm volatile("cp.async.wait_group 1;");
        } else {
            asm volatile("cp.async.wait_group 0;");
        }
        __syncthreads();

        const uint32_t base = smb + sc * STAGE_B;
        {
            const int c0 = (lane >> 4);
#pragma unroll
            for (int mi = 0; mi < 4; mi++)
                ldsm4(ah[0][mi], base + AH_OFF + arb[mi] + ((c0 ^ rswA[mi]) << 4));
#pragma unroll
            for (int ni = 0; ni < 4; ni++)
                ldsm4(bh[0][ni], base + BH_OFF + brb[ni] + ((c0 ^ rswB[ni]) << 4));
        }
#pragma unroll
        for (int ks = 0; ks < 4; ks++) {
            const int cur = ks & 1, nxt = cur ^ 1;
            const int c0c = ks * 2 + (lane >> 4);
#pragma unroll
            for (int mi = 0; mi < 4; mi++)
                ldsm4(al[mi], base + AL_OFF + arb[mi] + ((c0c ^ rswA[mi]) << 4));
            if (ks < 3) {
                const int c0n = (ks + 1) * 2 + (lane >> 4);
#pragma unroll
                for (int mi = 0; mi < 4; mi++)
                    ldsm4(ah[nxt][mi], base + AH_OFF + arb[mi] + ((c0n ^ rswA[mi]) << 4));
#pragma unroll
                for (int ni = 0; ni < 4; ni++)
                    ldsm4(bh[nxt][ni], base + BH_OFF + brb[ni] + ((c0n ^ rswB[ni]) << 4));
            }
#pragma unroll
            for (int mi = 0; mi < 4; mi++)
#pragma unroll
                for (int ni = 0; ni < 4; ni++)
#pragma unroll
                    for (int sel = 0; sel < 2; sel++)
                        mma16816h(acc[mi][ni * 2 + sel], ah[cur][mi],
                                  bh[cur][ni][sel], bh[cur][ni][sel + 2]);
#pragma unroll
            for (int mi = 0; mi < 4; mi++)
#pragma unroll
                for (int ni = 0; ni < 4; ni++)
#pragma unroll
                    for (int sel = 0; sel < 2; sel++)
                        mma16816h(acc[mi][ni * 2 + sel], al[mi],
                                  bh[cur][ni][sel], bh[cur][ni][sel + 2]);
        }
        sc = (sc == 2) ? 0 : sc + 1;
        sl = (sl == 2) ? 0 : sl + 1;
    }

    const int g = lane >> 2, t = lane & 3;
#pragma unroll
    for (int mi = 0; mi < 4; mi++) {
#pragma unroll
        for (int nj = 0; nj < 8; nj++) {
            const float* a = acc[mi][nj];
            int row = bm + wm + mi * 16 + g;
            int col = bn + wn + nj * 8 + t * 2;
            *(float2*)&C[(size_t)row * N + col] = make_float2(a[0], a[1]);
            *(float2*)&C[(size_t)(row + 8) * N + col] = make_float2(a[2], a[3]);
        }
    }
}

// ---------------------------------------------------------------------------
// Flash attention — exact round-12 champion version.
// ---------------------------------------------------------------------------
#define FA_SMEM (2 * 64 * 256)

__global__ __launch_bounds__(128) void flash_mma(
    const __half* __restrict__ qf_g,
    const __half* __restrict__ kf_g,
    const __half* __restrict__ vf_g,
    __half* __restrict__ attnh, __half* __restrict__ attnl)
{
    extern __shared__ char sm[];
    const uint32_t smb = smem_u32(sm);
    const uint32_t KO = 0, VO = 16384;
    const int tid = threadIdx.x, lane = tid & 31, w = tid >> 5;
    const int qi = blockIdx.x, h = blockIdx.y, b = blockIdx.z;
    const int sq0 = qi * 64;
    const int khd = h >> 2;
    const int g = lane >> 2, t4 = lane & 3;
    const int r0 = w * 16 + g, r1 = r0 + 8;

    uint32_t qf[8][4];
    {
        const __half* qb = qf_g + (((size_t)(b * NQ + h)) * SS + sq0) * DD;
#pragma unroll
        for (int ks = 0; ks < 8; ks++) {
            int c0 = ks * 16 + 2 * t4;
            qf[ks][0] = *(const uint32_t*)(qb + r0 * DD + c0);
            qf[ks][1] = *(const uint32_t*)(qb + r1 * DD + c0);
            qf[ks][2] = *(const uint32_t*)(qb + r0 * DD + c0 + 8);
            qf[ks][3] = *(const uint32_t*)(qb + r1 * DD + c0 + 8);
        }
    }

    uint32_t krb[4];
    int krsw[4];
#pragma unroll
    for (int kg = 0; kg < 4; kg++) {
        int r = kg * 16 + (lane & 15);
        krb[kg] = (uint32_t)(r * 256);
        krsw[kg] = r & 7;
    }

    float oacc[16][4];
#pragma unroll
    for (int i = 0; i < 16; i++)
#pragma unroll
        for (int j = 0; j < 4; j++) oacc[i][j] = 0.f;
    float m0 = -1e30f, m1 = -1e30f, l0 = 0.f, l1 = 0.f;

    const size_t kvb = ((size_t)(b * NKV + khd)) * TT * DD;
    const int nt = qi + 1 + PP / 64;

    for (int kt = 0; kt < nt; kt++) {
        __syncthreads();
        {
            const __half* srcK = kf_g + kvb + (size_t)kt * 64 * DD;
            const __half* srcV = vf_g + kvb + (size_t)kt * 64 * DD;
#pragma unroll
            for (int i = 0; i < 8; i++) {
                int id = tid + i * 128;
                int r = id >> 4, ch = id & 15;
                uint32_t sw = r * 256 + ((ch ^ (r & 7)) << 4);
                cp16(smb + KO + sw, srcK + r * DD + ch * 8);
                cp16(smb + VO + sw, srcV + r * DD + ch * 8);
            }
            asm volatile("cp.async.commit_group;");
            asm volatile("cp.async.wait_group 0;");
            __syncthreads();
        }

        float sacc[8][4];
#pragma unroll
        for (int j = 0; j < 8; j++)
#pragma unroll
            for (int e = 0; e < 4; e++) sacc[j][e] = 0.f;

        uint32_t kb[2][4][4];
        {
            const int c0 = (lane >> 4);
#pragma unroll
            for (int kg = 0; kg < 4; kg++)
                ldsm4(kb[0][kg], smb + KO + krb[kg] + ((c0 ^ krsw[kg]) << 4));
        }
#pragma unroll
        for (int ks = 0; ks < 8; ks++) {
            const int cur = ks & 1, nxt = cur ^ 1;
            if (ks < 7) {
                const int c0 = (ks + 1) * 2 + (lane >> 4);
#pragma unroll
                for (int kg = 0; kg < 4; kg++)
                    ldsm4(kb[nxt][kg], smb + KO + krb[kg] + ((c0 ^ krsw[kg]) << 4));
            }
#pragma unroll
            for (int kg = 0; kg < 4; kg++)
#pragma unroll
                for (int sel = 0; sel < 2; sel++)
                    mma16816h(sacc[kg * 2 + sel], qf[ks],
                              kb[cur][kg][sel], kb[cur][kg][sel + 2]);
        }

        if (kt == nt - 1) {
#pragma unroll
            for (int j = 0; j < 8; j++) {
                int cb = j * 8 + 2 * t4;
                if (cb     > r0) sacc[j][0] = -1e30f;
                if (cb + 1 > r0) sacc[j][1] = -1e30f;
                if (cb     > r1) sacc[j][2] = -1e30f;
                if (cb + 1 > r1) sacc[j][3] = -1e30f;
            }
        }

        float mx0 = m0, mx1 = m1;
#pragma unroll
        for (int j = 0; j < 8; j++) {
            mx0 = fmaxf(mx0, fmaxf(sacc[j][0], sacc[j][1]));
            mx1 = fmaxf(mx1, fmaxf(sacc[j][2], sacc[j][3]));
        }
        mx0 = fmaxf(mx0, __shfl_xor_sync(0xffffffff, mx0, 1));
        mx0 = fmaxf(mx0, __shfl_xor_sync(0xffffffff, mx0, 2));
        mx1 = fmaxf(mx1, __shfl_xor_sync(0xffffffff, mx1, 1));
        mx1 = fmaxf(mx1, __shfl_xor_sync(0xffffffff, mx1, 2));
        float rs0 = __expf(m0 - mx0), rs1 = __expf(m1 - mx1);
        m0 = mx0; m1 = mx1;
        l0 *= rs0; l1 *= rs1;

        uint32_t pf[4][4];
#pragma unroll
        for (int j = 0; j < 8; j++) {
            float p0 = __expf(sacc[j][0] - m0);
            float p1 = __expf(sacc[j][1] - m0);
            float p2 = __expf(sacc[j][2] - m1);
            float p3 = __expf(sacc[j][3] - m1);
            l0 += p0 + p1; l1 += p2 + p3;
            int kk = j >> 1, u = (j & 1) * 2;
            __half2 hA = __float22half2_rn(make_float2(p0, p1));
            __half2 hB = __float22half2_rn(make_float2(p2, p3));
            pf[kk][u]     = *(uint32_t*)&hA;
            pf[kk][u + 1] = *(uint32_t*)&hB;
        }

#pragma unroll
        for (int i = 0; i < 16; i++) {
            oacc[i][0] *= rs0; oacc[i][1] *= rs0;
            oacc[i][2] *= rs1; oacc[i][3] *= rs1;
        }

        uint32_t vfr[2][2][4];
        {
            int r = (lane & 15);
            int cA = (lane >> 4);
            int cB = 2 + (lane >> 4);
            ldsm4t(vfr[0][0], smb + VO + r * 256 + ((cA ^ (r & 7)) << 4));
            ldsm4t(vfr[0][1], smb + VO + r * 256 + ((cB ^ (r & 7)) << 4));
        }
#pragma unroll
        for (int idx = 0; idx < 16; idx++) {
            const int cur = idx & 1, nxt = cur ^ 1;
            const int kk = idx >> 2, dp = idx & 3;
            if (idx < 15) {
                const int kk2 = (idx + 1) >> 2, dp2 = (idx + 1) & 3;
                int r = kk2 * 16 + (lane & 15);
                int cA = dp2 * 4 + (lane >> 4);
                int cB = dp2 * 4 + 2 + (lane >> 4);
                ldsm4t(vfr[nxt][0], smb + VO + r * 256 + ((cA ^ (r & 7)) << 4));
                ldsm4t(vfr[nxt][1], smb + VO + r * 256 + ((cB ^ (r & 7)) << 4));
            }
            const int dg0 = dp * 2, dg1 = dp * 2 + 1;
            mma16816h(oacc[dg0 * 2],     pf[kk], vfr[cur][0][0], vfr[cur][0][1]);
            mma16816h(oacc[dg0 * 2 + 1], pf[kk], vfr[cur][0][2], vfr[cur][0][3]);
            mma16816h(oacc[dg1 * 2],     pf[kk], vfr[cur][1][0], vfr[cur][1][1]);
            mma16816h(oacc[dg1 * 2 + 1], pf[kk], vfr[cur][1][2], vfr[cur][1][3]);
        }
    }

    l0 += __shfl_xor_sync(0xffffffff, l0, 1);
    l0 += __shfl_xor_sync(0xffffffff, l0, 2);
    l1 += __shfl_xor_sync(0xffffffff, l1, 1);
    l1 += __shfl_xor_sync(0xffffffff, l1, 2);
    float inv0 = 1.f / l0, inv1 = 1.f / l1;

    size_t rowA = ((size_t)(b * SS + sq0 + r0)) * (NQ * DD) + h * DD;
    size_t rowB = ((size_t)(b * SS + sq0 + r1)) * (NQ * DD) + h * DD;
#pragma unroll
    for (int dt = 0; dt < 16; dt++) {
        int c = dt * 8 + 2 * t4;
        float v0 = oacc[dt][0] * inv0, v1 = oacc[dt][1] * inv0;
        float v2 = oacc[dt][2] * inv1, v3 = oacc[dt][3] * inv1;
        __half2 hA = __float22half2_rn(make_float2(v0, v1));
        float2 fA = __half22float2(hA);
        __half2 lA = __float22half2_rn(make_float2(v0 - fA.x, v1 - fA.y));
        __half2 hB = __float22half2_rn(make_float2(v2, v3));
        float2 fB = __half22float2(hB);
        __half2 lB = __float22half2_rn(make_float2(v2 - fB.x, v3 - fB.y));
        *(__half2*)&attnh[rowA + c] = hA;
        *(__half2*)&attnl[rowA + c] = lA;
        *(__half2*)&attnh[rowB + c] = hB;
        *(__half2*)&attnl[rowB + c] = lB;
    }
}

// ---------------------------------------------------------------------------
extern "C" void kernel_launch(void* const* d_in, const int* in_sizes, int n_in,
                              void* d_out, int out_size)
{
    const float* hidden = (const float*)d_in[0];
    const float* w_qkv  = (const float*)d_in[1];
    const float* w_o    = (const float*)d_in[2];
    const float* cosb   = (const float*)d_in[3];
    const float* sinb   = (const float*)d_in[4];
    const float* kc     = (const float*)d_in[5];
    const float* vc     = (const float*)d_in[6];
    float* out = (float*)d_out;

    __half *hidf, *wq, *wo, *ath, *atl, *qf, *kf, *vf;
    cudaGetSymbolAddress((void**)&hidf, g_hid);
    cudaGetSymbolAddress((void**)&wq, g_wqkv);
    cudaGetSymbolAddress((void**)&wo, g_wo);
    cudaGetSymbolAddress((void**)&ath, g_attn_h);
    cudaGetSymbolAddress((void**)&atl, g_attn_l);
    cudaGetSymbolAddress((void**)&qf, g_q_f);
    cudaGetSymbolAddress((void**)&kf, g_k_f);
    cudaGetSymbolAddress((void**)&vf, g_v_f);

    cudaFuncSetAttribute(gemm_qkv_fused,
                         cudaFuncAttributeMaxDynamicSharedMemorySize, GEMM1_SMEM);
    cudaFuncSetAttribute(gemm_f16x2,
                         cudaFuncAttributeMaxDynamicSharedMemorySize, GEMM_SMEM);
    cudaFuncSetAttribute(flash_mma,
                         cudaFuncAttributeMaxDynamicSharedMemorySize, FA_SMEM);

    const int M = BB * SS;  // 2048

    // 0) activation convert + weight transposes + KV-cache conversion
    {
        int n = M * HH;
        conv_f16<<<(n + 255) / 256, 256>>>(hidden, hidf, n);
        trans_f16<<<dim3(QKVN / 32, HH / 32), dim3(32, 8)>>>(w_qkv, wq, HH, QKVN);
        trans_f16<<<dim3(HH / 32, HH / 32), dim3(32, 8)>>>(w_o, wo, HH, HH);
        conv_cache_f16<<<(CACHETOT + 255) / 256, 256>>>(kc, vc, kf, vf);
    }
    // 1) QKV projection fused with RoPE + fp16 q/k/v scatter
    gemm_qkv_fused<<<dim3(QKVN / 256, M / 128), 256, GEMM1_SMEM>>>(
        hidf, wq, cosb, sinb, qf, kf, vf, M, QKVN, HH);
    // 2) Flash attention
    flash_mma<<<dim3(SS / 64, NQ, BB), 128, FA_SMEM>>>(qf, kf, vf, ath, atl);
    // 3) Output projection (fp16x2)
    gemm_f16x2<<<dim3(HH / 256, M / 128), 256, GEMM_SMEM>>>(
        ath, atl, wo, out, M, HH, HH);
}

// round 16
// speedup vs baseline: 1.0447x; 1.0447x over previous
#include <cuda_runtime.h>
#include <cuda_bf16.h>
#include <cuda_fp16.h>
#include <math.h>
#include <stdint.h>

// Problem constants
#define BB   2
#define SS   1024
#define PP   1024
#define TT   (PP + SS)
#define HH   4096
#define NQ   32
#define NKV  8
#define DD   128
#define QKVN ((NQ + 2 * NKV) * DD)   // 6144
#define SCALE 0.08838834764831845f   // 1/sqrt(128)

// ---------------------------------------------------------------------------
// Scratch (device globals: no allocation allowed)
// ---------------------------------------------------------------------------
__device__ float g_qkv[BB * SS * QKVN];
__device__ __half g_hid[BB * SS * HH];
__device__ __half g_wqkv[(size_t)QKVN * HH];         // transposed [N,K]
__device__ __half g_wo[(size_t)HH * HH];             // transposed [N,K]
__device__ __half g_attn_h[BB * SS * NQ * DD];
__device__ __half g_attn_l[BB * SS * NQ * DD];
__device__ __half g_q_f[(size_t)BB * NQ * SS * DD];
__device__ __half g_k_f[(size_t)BB * NKV * TT * DD];
__device__ __half g_v_f[(size_t)BB * NKV * TT * DD];

// ---------------------------------------------------------------------------
// Low-level helpers (plain sm_80+ ISA)
// ---------------------------------------------------------------------------
__device__ __forceinline__ uint32_t smem_u32(const void* p) {
    uint32_t a;
    asm("{ .reg .u64 t; cvta.to.shared.u64 t, %1; cvt.u32.u64 %0, t; }"
        : "=r"(a) : "l"(p));
    return a;
}
__device__ __forceinline__ void cp16(uint32_t dst, const void* src) {
    asm volatile("cp.async.cg.shared.global [%0], [%1], 16;"
                 :: "r"(dst), "l"(src));
}
__device__ __forceinline__ void ldsm4(uint32_t* r, uint32_t a) {
    asm volatile("ldmatrix.sync.aligned.m8n8.x4.shared.b16 {%0,%1,%2,%3}, [%4];"
                 : "=r"(r[0]), "=r"(r[1]), "=r"(r[2]), "=r"(r[3]) : "r"(a));
}
__device__ __forceinline__ void ldsm4t(uint32_t* r, uint32_t a) {
    asm volatile("ldmatrix.sync.aligned.m8n8.x4.trans.shared.b16 {%0,%1,%2,%3}, [%4];"
                 : "=r"(r[0]), "=r"(r[1]), "=r"(r[2]), "=r"(r[3]) : "r"(a));
}
__device__ __forceinline__ void mma16816h(float* c, const uint32_t* a,
                                          const uint32_t b0, const uint32_t b1) {
    asm volatile(
        "mma.sync.aligned.m16n8k16.row.col.f32.f16.f16.f32 "
        "{%0,%1,%2,%3}, {%4,%5,%6,%7}, {%8,%9}, {%0,%1,%2,%3};"
        : "+f"(c[0]), "+f"(c[1]), "+f"(c[2]), "+f"(c[3])
        : "r"(a[0]), "r"(a[1]), "r"(a[2]), "r"(a[3]), "r"(b0), "r"(b1));
}

// ---------------------------------------------------------------------------
// fp32 -> fp16 convert (GEMM1 activations)
// ---------------------------------------------------------------------------
__global__ void conv_f16(const float* __restrict__ x,
                         __half* __restrict__ xo, int n)
{
    int i = blockIdx.x * blockDim.x + threadIdx.x;
    if (i >= n) return;
    xo[i] = __float2half(x[i]);
}

// fp32 [R,C] -> fp16 transposed [C,R] (weights)
__global__ void trans_f16(const float* __restrict__ x,
                          __half* __restrict__ xo, int R, int C)
{
    __shared__ float t[32][33];
    int r0 = blockIdx.y * 32, c0 = blockIdx.x * 32;
    int tx = threadIdx.x, ty = threadIdx.y;
#pragma unroll
    for (int j = 0; j < 4; j++)
        t[ty + 8 * j][tx] = x[(size_t)(r0 + ty + 8 * j) * C + c0 + tx];
    __syncthreads();
#pragma unroll
    for (int j = 0; j < 4; j++)
        xo[(size_t)(c0 + ty + 8 * j) * R + r0 + tx] = __float2half(t[tx][ty + 8 * j]);
}

// ---------------------------------------------------------------------------
// fp16 single-pass GEMM (QKV): round-12 champion config.
// ---------------------------------------------------------------------------
#define X1_A_OFF 0
#define X1_B_OFF 16384
#define X1_STAGE 49152
#define GEMM1_SMEM (3 * X1_STAGE)

#define LOAD_STAGE1(c, s) do {                                             \
    int _k0 = (c) * 64;                                                    \
    uint32_t _stb = smb + (s) * X1_STAGE;                                  \
    _Pragma("unroll")                                                      \
    for (int _i = 0; _i < 4; _i++) {                                       \
        int _id = tid + _i * 256;                                          \
        int _row = _id >> 3, _ch = _id & 7;                                \
        uint32_t _sw = (_row << 7) + ((_ch ^ (_row & 7)) << 4);            \
        cp16(_stb + X1_A_OFF + _sw, srcA + (size_t)_row * K + _k0 + _ch * 8); \
    }                                                                      \
    _Pragma("unroll")                                                      \
    for (int _i = 0; _i < 8; _i++) {                                       \
        int _id = tid + _i * 256;                                          \
        int _row = _id >> 3, _ch = _id & 7;                                \
        uint32_t _sw = (_row << 7) + ((_ch ^ (_row & 7)) << 4);            \
        cp16(_stb + X1_B_OFF + _sw, srcB + (size_t)_row * K + _k0 + _ch * 8); \
    }                                                                      \
    asm volatile("cp.async.commit_group;");                                \
} while (0)

__global__ __launch_bounds__(256, 1) void gemm_f16x1(
    const __half* __restrict__ A, const __half* __restrict__ B,
    float* __restrict__ C, int M, int N, int K)
{
    extern __shared__ char sm[];
    const uint32_t smb = smem_u32(sm);
    const int tid = threadIdx.x;
    const int wid = tid >> 5, lane = tid & 31;
    const int bm = blockIdx.y * 128, bn = blockIdx.x * 256;
    const int wm = (wid & 1) * 64, wn = (wid >> 1) * 64;

    const __half* srcA = A + (size_t)bm * K;
    const __half* srcB = B + (size_t)bn * K;

    uint32_t arb[4], brb[4];
    int rswA[4], rswB[4];
#pragma unroll
    for (int mi = 0; mi < 4; mi++) {
        int row = wm + mi * 16 + (lane & 15);
        arb[mi] = (uint32_t)(row << 7) + X1_A_OFF;
        rswA[mi] = row & 7;
    }
#pragma unroll
    for (int ni = 0; ni < 4; ni++) {
        int row = wn + ni * 16 + (lane & 15);
        brb[ni] = (uint32_t)(row << 7) + X1_B_OFF;
        rswB[ni] = row & 7;
    }

    float acc[4][8][4];
#pragma unroll
    for (int i = 0; i < 4; i++)
#pragma unroll
        for (int j = 0; j < 8; j++)
#pragma unroll
            for (int e = 0; e < 4; e++) acc[i][j][e] = 0.f;

    const int NC = K / 64;
    LOAD_STAGE1(0, 0);
    LOAD_STAGE1(1, 1);

    uint32_t ah[2][4][4], bh[2][4][4];
    int sc = 0, sl = 2;
    for (int c = 0; c < NC; c++) {
        __syncthreads();
        if (c + 2 < NC) {
            LOAD_STAGE1(c + 2, sl);
            asm volatile("cp.async.wait_group 2;");
        } else if (c + 1 < NC) {
            asm volatile("cp.async.wait_group 1;");
        } else {
            asm volatile("cp.async.wait_group 0;");
        }
        __syncthreads();

        const uint32_t base = smb + sc * X1_STAGE;
        {
            const int c0 = (lane >> 4);
#pragma unroll
            for (int mi = 0; mi < 4; mi++)
                ldsm4(ah[0][mi], base + arb[mi] + ((c0 ^ rswA[mi]) << 4));
#pragma unroll
            for (int ni = 0; ni < 4; ni++)
                ldsm4(bh[0][ni], base + brb[ni] + ((c0 ^ rswB[ni]) << 4));
        }
#pragma unroll
        for (int ks = 0; ks < 4; ks++) {
            const int cur = ks & 1, nxt = cur ^ 1;
            if (ks < 3) {
                const int c0 = (ks + 1) * 2 + (lane >> 4);
#pragma unroll
                for (int mi = 0; mi < 4; mi++)
                    ldsm4(ah[nxt][mi], base + arb[mi] + ((c0 ^ rswA[mi]) << 4));
#pragma unroll
                for (int ni = 0; ni < 4; ni++)
                    ldsm4(bh[nxt][ni], base + brb[ni] + ((c0 ^ rswB[ni]) << 4));
            }
#pragma unroll
            for (int mi = 0; mi < 4; mi++)
#pragma unroll
                for (int ni = 0; ni < 4; ni++)
#pragma unroll
                    for (int sel = 0; sel < 2; sel++)
                        mma16816h(acc[mi][ni * 2 + sel], ah[cur][mi],
                                  bh[cur][ni][sel], bh[cur][ni][sel + 2]);
        }
        sc = (sc == 2) ? 0 : sc + 1;
        sl = (sl == 2) ? 0 : sl + 1;
    }

    const int g = lane >> 2, t = lane & 3;
#pragma unroll
    for (int mi = 0; mi < 4; mi++) {
#pragma unroll
        for (int nj = 0; nj < 8; nj++) {
            const float* a = acc[mi][nj];
            int row = bm + wm + mi * 16 + g;
            int col = bn + wn + nj * 8 + t * 2;
            *(float2*)&C[(size_t)row * N + col] = make_float2(a[0], a[1]);
            *(float2*)&C[(size_t)(row + 8) * N + col] = make_float2(a[2], a[3]);
        }
    }
}

// ---------------------------------------------------------------------------
// fp16x2 GEMM (output projection) — round-12 version, unchanged.
// ---------------------------------------------------------------------------
#define AH_OFF 0
#define AL_OFF 16384
#define BH_OFF 32768
#define STAGE_B  65536
#define GEMM_SMEM (3 * STAGE_B)

#define LOAD_STAGE(c, s) do {                                              \
    int _k0 = (c) * 64;                                                    \
    uint32_t _stb = smb + (s) * STAGE_B;                                   \
    _Pragma("unroll")                                                      \
    for (int _i = 0; _i < 4; _i++) {                                       \
        int _id = tid + _i * 256;                                          \
        int _row = _id >> 3, _ch = _id & 7;                                \
        uint32_t _sw = (_row << 7) + ((_ch ^ (_row & 7)) << 4);            \
        const size_t _go = (size_t)_row * K + _k0 + _ch * 8;               \
        cp16(_stb + AH_OFF + _sw, srcAh + _go);                            \
        cp16(_stb + AL_OFF + _sw, srcAl + _go);                            \
    }                                                                      \
    _Pragma("unroll")                                                      \
    for (int _i = 0; _i < 8; _i++) {                                       \
        int _id = tid + _i * 256;                                          \
        int _row = _id >> 3, _ch = _id & 7;                                \
        uint32_t _sw = (_row << 7) + ((_ch ^ (_row & 7)) << 4);            \
        cp16(_stb + BH_OFF + _sw, srcB + (size_t)_row * K + _k0 + _ch * 8); \
    }                                                                      \
    asm volatile("cp.async.commit_group;");                                \
} while (0)

__global__ __launch_bounds__(256, 1) void gemm_f16x2(
    const __half* __restrict__ Ah, const __half* __restrict__ Al,
    const __half* __restrict__ B,
    float* __restrict__ C, int M, int N, int K)
{
    extern __shared__ char sm[];
    const uint32_t smb = smem_u32(sm);
    const int tid = threadIdx.x;
    const int wid = tid >> 5, lane = tid & 31;
    const int bm = blockIdx.y * 128, bn = blockIdx.x * 256;
    const int wm = (wid & 1) * 64, wn = (wid >> 1) * 64;

    const __half* srcAh = Ah + (size_t)bm * K;
    const __half* srcAl = Al + (size_t)bm * K;
    const __half* srcB  = B  + (size_t)bn * K;

    uint32_t arb[4], brb[4];
    int rswA[4], rswB[4];
#pragma unroll
    for (int mi = 0; mi < 4; mi++) {
        int row = wm + mi * 16 + (lane & 15);
        arb[mi] = (uint32_t)(row << 7);
        rswA[mi] = row & 7;
    }
#pragma unroll
    for (int ni = 0; ni < 4; ni++) {
        int row = wn + ni * 16 + (lane & 15);
        brb[ni] = (uint32_t)(row << 7);
        rswB[ni] = row & 7;
    }

    float acc[4][8][4];
#pragma unroll
    for (int i = 0; i < 4; i++)
#pragma unroll
        for (int j = 0; j < 8; j++)
#pragma unroll
            for (int e = 0; e < 4; e++) acc[i][j][e] = 0.f;

    const int NC = K / 64;
    LOAD_STAGE(0, 0);
    LOAD_STAGE(1, 1);

    uint32_t ah[2][4][4], bh[2][4][4], al[4][4];
    int sc = 0, sl = 2;
    for (int c = 0; c < NC; c++) {
        __syncthreads();
        if (c + 2 < NC) {
            LOAD_STAGE(c + 2, sl);
            asm volatile("cp.async.wait_group 2;");
        } else if (c + 1 < NC) {
            asm volatile("cp.async.wait_group 1;");
        } else {
            asm volatile("cp.async.wait_group 0;");
        }
        __syncthreads();

        const uint32_t base = smb + sc * STAGE_B;
        {
            const int c0 = (lane >> 4);
#pragma unroll
            for (int mi = 0; mi < 4; mi++)
                ldsm4(ah[0][mi], base + AH_OFF + arb[mi] + ((c0 ^ rswA[mi]) << 4));
#pragma unroll
            for (int ni = 0; ni < 4; ni++)
                ldsm4(bh[0][ni], base + BH_OFF + brb[ni] + ((c0 ^ rswB[ni]) << 4));
        }
#pragma unroll
        for (int ks = 0; ks < 4; ks++) {
            const int cur = ks & 1, nxt = cur ^ 1;
            const int c0c = ks * 2 + (lane >> 4);
#pragma unroll
            for (int mi = 0; mi < 4; mi++)
                ldsm4(al[mi], base + AL_OFF + arb[mi] + ((c0c ^ rswA[mi]) << 4));
            if (ks < 3) {
                const int c0n = (ks + 1) * 2 + (lane >> 4);
#pragma unroll
                for (int mi = 0; mi < 4; mi++)
                    ldsm4(ah[nxt][mi], base + AH_OFF + arb[mi] + ((c0n ^ rswA[mi]) << 4));
#pragma unroll
                for (int ni = 0; ni < 4; ni++)
                    ldsm4(bh[nxt][ni], base + BH_OFF + brb[ni] + ((c0n ^ rswB[ni]) << 4));
            }
#pragma unroll
            for (int mi = 0; mi < 4; mi++)
#pragma unroll
                for (int ni = 0; ni < 4; ni++)
#pragma unroll
                    for (int sel = 0; sel < 2; sel++)
                        mma16816h(acc[mi][ni * 2 + sel], ah[cur][mi],
                                  bh[cur][ni][sel], bh[cur][ni][sel + 2]);
#pragma unroll
            for (int mi = 0; mi < 4; mi++)
#pragma unroll
                for (int ni = 0; ni < 4; ni++)
#pragma unroll
                    for (int sel = 0; sel < 2; sel++)
                        mma16816h(acc[mi][ni * 2 + sel], al[mi],
                                  bh[cur][ni][sel], bh[cur][ni][sel + 2]);
        }
        sc = (sc == 2) ? 0 : sc + 1;
        sl = (sl == 2) ? 0 : sl + 1;
    }

    const int g = lane >> 2, t = lane & 3;
#pragma unroll
    for (int mi = 0; mi < 4; mi++) {
#pragma unroll
        for (int nj = 0; nj < 8; nj++) {
            const float* a = acc[mi][nj];
            int row = bm + wm + mi * 16 + g;
            int col = bn + wn + nj * 8 + t * 2;
            *(float2*)&C[(size_t)row * N + col] = make_float2(a[0], a[1]);
            *(float2*)&C[(size_t)(row + 8) * N + col] = make_float2(a[2], a[3]);
        }
    }
}

// ---------------------------------------------------------------------------
// Fused pre-pass (round-12 version)
// ---------------------------------------------------------------------------
#define NQTOT (BB * SS * NQ * 64)
#define KVTOT (BB * NKV * TT * 64)

__global__ void prep_qkv_f16(const float* __restrict__ qkv,
                             const float* __restrict__ kcache,
                             const float* __restrict__ vcache,
                             const float* __restrict__ cosb,
                             const float* __restrict__ sinb,
                             __half* __restrict__ qf,
                             __half* __restrict__ kf, __half* __restrict__ vf)
{
    int idx = blockIdx.x * blockDim.x + threadIdx.x;
    if (idx < NQTOT) {
        int d = idx & 63;
        int rest = idx >> 6;
        int h = rest % NQ;
        int s = (rest / NQ) % SS;
        int b = rest / (NQ * SS);
        const float* base = &qkv[((size_t)(b * SS + s)) * QKVN + h * DD];
        float x1 = base[d], x2 = base[d + 64];
        float c0 = cosb[s * DD + d],      s0 = sinb[s * DD + d];
        float c1 = cosb[s * DD + d + 64], s1 = sinb[s * DD + d + 64];
        size_t o = (((size_t)(b * NQ + h)) * SS + s) * DD + d;
        qf[o]      = __float2half((x1 * c0 - x2 * s0) * SCALE);
        qf[o + 64] = __float2half((x2 * c1 + x1 * s1) * SCALE);
        return;
    }
    idx -= NQTOT;
    if (idx >= KVTOT) return;
    int d = idx & 63;
    int rest = idx >> 6;
    int t = rest % TT;
    int kh = (rest / TT) % NKV;
    int b = rest / (TT * NKV);

    float k1, k2, v1, v2;
    if (t < PP) {
        size_t src = (((size_t)(b * PP + t)) * NKV + kh) * DD;
        k1 = kcache[src + d]; k2 = kcache[src + d + 64];
        v1 = vcache[src + d]; v2 = vcache[src + d + 64];
    } else {
        int s = t - PP;
        const float* base = &qkv[((size_t)(b * SS + s)) * QKVN];
        float x1 = base[(NQ + kh) * DD + d], x2 = base[(NQ + kh) * DD + d + 64];
        float c0 = cosb[s * DD + d],      s0 = sinb[s * DD + d];
        float c1 = cosb[s * DD + d + 64], s1 = sinb[s * DD + d + 64];
        k1 = x1 * c0 - x2 * s0;
        k2 = x2 * c1 + x1 * s1;
        v1 = base[(NQ + NKV + kh) * DD + d];
        v2 = base[(NQ + NKV + kh) * DD + d + 64];
    }
    size_t o = (((size_t)(b * NKV + kh)) * TT + t) * DD + d;
    kf[o]      = __float2half(k1);
    kf[o + 64] = __float2half(k2);
    vf[o]      = __float2half(v1);
    vf[o + 64] = __float2half(v2);
}

// ---------------------------------------------------------------------------
// Flash attention: 2 GQA q-heads per CTA share one K/V smem tile.
// 256 threads: warps 0-3 -> head h0 (64 queries), warps 4-7 -> head h1.
// Per-warp math identical to round-12 flash.
// ---------------------------------------------------------------------------
#define FA_SMEM (2 * 64 * 256)   // K 16KB + V 16KB

__global__ __launch_bounds__(256) void flash_mma(
    const __half* __restrict__ qf_g,
    const __half* __restrict__ kf_g,
    const __half* __restrict__ vf_g,
    __half* __restrict__ attnh, __half* __restrict__ attnl)
{
    extern __shared__ char sm[];
    const uint32_t smb = smem_u32(sm);
    const uint32_t KO = 0, VO = 16384;
    const int tid = threadIdx.x, lane = tid & 31, w = tid >> 5;
    const int wl = w & 3;            // warp-in-head
    const int hp = w >> 2;           // head-in-pair
    const int qi = blockIdx.x, b = blockIdx.z;
    const int h = blockIdx.y * 2 + hp;
    const int sq0 = qi * 64;
    const int khd = h >> 2;          // same for both heads in the pair
    const int g = lane >> 2, t4 = lane & 3;
    const int r0 = wl * 16 + g, r1 = r0 + 8;

    uint32_t qf[8][4];
    {
        const __half* qb = qf_g + (((size_t)(b * NQ + h)) * SS + sq0) * DD;
#pragma unroll
        for (int ks = 0; ks < 8; ks++) {
            int c0 = ks * 16 + 2 * t4;
            qf[ks][0] = *(const uint32_t*)(qb + r0 * DD + c0);
            qf[ks][1] = *(const uint32_t*)(qb + r1 * DD + c0);
            qf[ks][2] = *(const uint32_t*)(qb + r0 * DD + c0 + 8);
            qf[ks][3] = *(const uint32_t*)(qb + r1 * DD + c0 + 8);
        }
    }

    uint32_t krb[4];
    int krsw[4];
#pragma unroll
    for (int kg = 0; kg < 4; kg++) {
        int r = kg * 16 + (lane & 15);
        krb[kg] = (uint32_t)(r * 256);
        krsw[kg] = r & 7;
    }

    float oacc[16][4];
#pragma unroll
    for (int i = 0; i < 16; i++)
#pragma unroll
        for (int j = 0; j < 4; j++) oacc[i][j] = 0.f;
    float m0 = -1e30f, m1 = -1e30f, l0 = 0.f, l1 = 0.f;

    const size_t kvb = ((size_t)(b * NKV + khd)) * TT * DD;
    const int nt = qi + 1 + PP / 64;

    for (int kt = 0; kt < nt; kt++) {
        __syncthreads();
        {
            const __half* srcK = kf_g + kvb + (size_t)kt * 64 * DD;
            const __half* srcV = vf_g + kvb + (size_t)kt * 64 * DD;
#pragma unroll
            for (int i = 0; i < 4; i++) {
                int id = tid + i * 256;
                int r = id >> 4, ch = id & 15;
                uint32_t sw = r * 256 + ((ch ^ (r & 7)) << 4);
                cp16(smb + KO + sw, srcK + r * DD + ch * 8);
                cp16(smb + VO + sw, srcV + r * DD + ch * 8);
            }
            asm volatile("cp.async.commit_group;");
            asm volatile("cp.async.wait_group 0;");
            __syncthreads();
        }

        float sacc[8][4];
#pragma unroll
        for (int j = 0; j < 8; j++)
#pragma unroll
            for (int e = 0; e < 4; e++) sacc[j][e] = 0.f;

        uint32_t kb[2][4][4];
        {
            const int c0 = (lane >> 4);
#pragma unroll
            for (int kg = 0; kg < 4; kg++)
                ldsm4(kb[0][kg], smb + KO + krb[kg] + ((c0 ^ krsw[kg]) << 4));
        }
#pragma unroll
        for (int ks = 0; ks < 8; ks++) {
            const int cur = ks & 1, nxt = cur ^ 1;
            if (ks < 7) {
                const int c0 = (ks + 1) * 2 + (lane >> 4);
#pragma unroll
                for (int kg = 0; kg < 4; kg++)
                    ldsm4(kb[nxt][kg], smb + KO + krb[kg] + ((c0 ^ krsw[kg]) << 4));
            }
#pragma unroll
            for (int kg = 0; kg < 4; kg++)
#pragma unroll
                for (int sel = 0; sel < 2; sel++)
                    mma16816h(sacc[kg * 2 + sel], qf[ks],
                              kb[cur][kg][sel], kb[cur][kg][sel + 2]);
        }

        if (kt == nt - 1) {
#pragma unroll
            for (int j = 0; j < 8; j++) {
                int cb = j * 8 + 2 * t4;
                if (cb     > r0) sacc[j][0] = -1e30f;
                if (cb + 1 > r0) sacc[j][1] = -1e30f;
                if (cb     > r1) sacc[j][2] = -1e30f;
                if (cb + 1 > r1) sacc[j][3] = -1e30f;
            }
        }

        float mx0 = m0, mx1 = m1;
#pragma unroll
        for (int j = 0; j < 8; j++) {
            mx0 = fmaxf(mx0, fmaxf(sacc[j][0], sacc[j][1]));
            mx1 = fmaxf(mx1, fmaxf(sacc[j][2], sacc[j][3]));
        }
        mx0 = fmaxf(mx0, __shfl_xor_sync(0xffffffff, mx0, 1));
        mx0 = fmaxf(mx0, __shfl_xor_sync(0xffffffff, mx0, 2));
        mx1 = fmaxf(mx1, __shfl_xor_sync(0xffffffff, mx1, 1));
        mx1 = fmaxf(mx1, __shfl_xor_sync(0xffffffff, mx1, 2));
        float rs0 = __expf(m0 - mx0), rs1 = __expf(m1 - mx1);
        m0 = mx0; m1 = mx1;
        l0 *= rs0; l1 *= rs1;

        uint32_t pf[4][4];
#pragma unroll
        for (int j = 0; j < 8; j++) {
            float p0 = __expf(sacc[j][0] - m0);
            float p1 = __expf(sacc[j][1] - m0);
            float p2 = __expf(sacc[j][2] - m1);
            float p3 = __expf(sacc[j][3] - m1);
            l0 += p0 + p1; l1 += p2 + p3;
            int kk = j >> 1, u = (j & 1) * 2;
            __half2 hA = __float22half2_rn(make_float2(p0, p1));
            __half2 hB = __float22half2_rn(make_float2(p2, p3));
            pf[kk][u]     = *(uint32_t*)&hA;
            pf[kk][u + 1] = *(uint32_t*)&hB;
        }

#pragma unroll
        for (int i = 0; i < 16; i++) {
            oacc[i][0] *= rs0; oacc[i][1] *= rs0;
            oacc[i][2] *= rs1; oacc[i][3] *= rs1;
        }

        uint32_t vfr[2][2][4];
        {
            int r = (lane & 15);
            int cA = (lane >> 4);
            int cB = 2 + (lane >> 4);
            ldsm4t(vfr[0][0], smb + VO + r * 256 + ((cA ^ (r & 7)) << 4));
            ldsm4t(vfr[0][1], smb + VO + r * 256 + ((cB ^ (r & 7)) << 4));
        }
#pragma unroll
        for (int idx = 0; idx < 16; idx++) {
            const int cur = idx & 1, nxt = cur ^ 1;
            const int kk = idx >> 2, dp = idx & 3;
            if (idx < 15) {
                const int kk2 = (idx + 1) >> 2, dp2 = (idx + 1) & 3;
                int r = kk2 * 16 + (lane & 15);
                int cA = dp2 * 4 + (lane >> 4);
                int cB = dp2 * 4 + 2 + (lane >> 4);
                ldsm4t(vfr[nxt][0], smb + VO + r * 256 + ((cA ^ (r & 7)) << 4));
                ldsm4t(vfr[nxt][1], smb + VO + r * 256 + ((cB ^ (r & 7)) << 4));
            }
            const int dg0 = dp * 2, dg1 = dp * 2 + 1;
            mma16816h(oacc[dg0 * 2],     pf[kk], vfr[cur][0][0], vfr[cur][0][1]);
            mma16816h(oacc[dg0 * 2 + 1], pf[kk], vfr[cur][0][2], vfr[cur][0][3]);
            mma16816h(oacc[dg1 * 2],     pf[kk], vfr[cur][1][0], vfr[cur][1][1]);
            mma16816h(oacc[dg1 * 2 + 1], pf[kk], vfr[cur][1][2], vfr[cur][1][3]);
        }
    }

    l0 += __shfl_xor_sync(0xffffffff, l0, 1);
    l0 += __shfl_xor_sync(0xffffffff, l0, 2);
    l1 += __shfl_xor_sync(0xffffffff, l1, 1);
    l1 += __shfl_xor_sync(0xffffffff, l1, 2);
    float inv0 = 1.f / l0, inv1 = 1.f / l1;

    size_t rowA = ((size_t)(b * SS + sq0 + r0)) * (NQ * DD) + h * DD;
    size_t rowB = ((size_t)(b * SS + sq0 + r1)) * (NQ * DD) + h * DD;
#pragma unroll
    for (int dt = 0; dt < 16; dt++) {
        int c = dt * 8 + 2 * t4;
        float v0 = oacc[dt][0] * inv0, v1 = oacc[dt][1] * inv0;
        float v2 = oacc[dt][2] * inv1, v3 = oacc[dt][3] * inv1;
        __half2 hA = __float22half2_rn(make_float2(v0, v1));
        float2 fA = __half22float2(hA);
        __half2 lA = __float22half2_rn(make_float2(v0 - fA.x, v1 - fA.y));
        __half2 hB = __float22half2_rn(make_float2(v2, v3));
        float2 fB = __half22float2(hB);
        __half2 lB = __float22half2_rn(make_float2(v2 - fB.x, v3 - fB.y));
        *(__half2*)&attnh[rowA + c] = hA;
        *(__half2*)&attnl[rowA + c] = lA;
        *(__half2*)&attnh[rowB + c] = hB;
        *(__half2*)&attnl[rowB + c] = lB;
    }
}

// ---------------------------------------------------------------------------
extern "C" void kernel_launch(void* const* d_in, const int* in_sizes, int n_in,
                              void* d_out, int out_size)
{
    const float* hidden = (const float*)d_in[0];
    const float* w_qkv  = (const float*)d_in[1];
    const float* w_o    = (const float*)d_in[2];
    const float* cosb   = (const float*)d_in[3];
    const float* sinb   = (const float*)d_in[4];
    const float* kc     = (const float*)d_in[5];
    const float* vc     = (const float*)d_in[6];
    float* out = (float*)d_out;

    float *qkv;
    __half *hidf, *wq, *wo, *ath, *atl, *qf, *kf, *vf;
    cudaGetSymbolAddress((void**)&qkv, g_qkv);
    cudaGetSymbolAddress((void**)&hidf, g_hid);
    cudaGetSymbolAddress((void**)&wq, g_wqkv);
    cudaGetSymbolAddress((void**)&wo, g_wo);
    cudaGetSymbolAddress((void**)&ath, g_attn_h);
    cudaGetSymbolAddress((void**)&atl, g_attn_l);
    cudaGetSymbolAddress((void**)&qf, g_q_f);
    cudaGetSymbolAddress((void**)&kf, g_k_f);
    cudaGetSymbolAddress((void**)&vf, g_v_f);

    cudaFuncSetAttribute(gemm_f16x1,
                         cudaFuncAttributeMaxDynamicSharedMemorySize, GEMM1_SMEM);
    cudaFuncSetAttribute(gemm_f16x2,
                         cudaFuncAttributeMaxDynamicSharedMemorySize, GEMM_SMEM);
    cudaFuncSetAttribute(flash_mma,
                         cudaFuncAttributeMaxDynamicSharedMemorySize, FA_SMEM);

    const int M = BB * SS;  // 2048

    // 0) activation convert + weight transposes
    {
        int n = M * HH;
        conv_f16<<<(n + 255) / 256, 256>>>(hidden, hidf, n);
        trans_f16<<<dim3(QKVN / 32, HH / 32), dim3(32, 8)>>>(w_qkv, wq, HH, QKVN);
        trans_f16<<<dim3(HH / 32, HH / 32), dim3(32, 8)>>>(w_o, wo, HH, HH);
    }
    // 1) QKV projection (fp16 single-pass)
    gemm_f16x1<<<dim3(QKVN / 256, M / 128), 256, GEMM1_SMEM>>>(
        hidf, wq, qkv, M, QKVN, HH);
    // 2) fused pre-pass
    {
        int total = NQTOT + KVTOT;
        prep_qkv_f16<<<(total + 255) / 256, 256>>>(qkv, kc, vc, cosb, sinb,
                                                   qf, kf, vf);
    }
    // 3) Flash attention (2 GQA heads per CTA share K/V)
    flash_mma<<<dim3(SS / 64, NQ / 2, BB), 256, FA_SMEM>>>(qf, kf, vf, ath, atl);
    // 4) Output projection (fp16x2)
    gemm_f16x2<<<dim3(HH / 256, M / 128), 256, GEMM_SMEM>>>(
        ath, atl, wo, out, M, HH, HH);
}

// round 17
// speedup vs baseline: 1.1081x; 1.0607x over previous
#include <cuda_runtime.h>
#include <cuda_bf16.h>
#include <cuda_fp16.h>
#include <math.h>
#include <stdint.h>

// Problem constants
#define BB   2
#define SS   1024
#define PP   1024
#define TT   (PP + SS)
#define HH   4096
#define NQ   32
#define NKV  8
#define DD   128
#define QKVN ((NQ + 2 * NKV) * DD)   // 6144
#define SCALE 0.08838834764831845f   // 1/sqrt(128)

// ---------------------------------------------------------------------------
// Scratch (device globals: no allocation allowed)
// ---------------------------------------------------------------------------
__device__ float g_qkv[BB * SS * QKVN];
__device__ __half g_hid[BB * SS * HH];
__device__ __half g_wqkv[(size_t)QKVN * HH];         // transposed [N,K]
__device__ __half g_wo[(size_t)HH * HH];             // transposed [N,K]
__device__ __half g_attn_h[BB * SS * NQ * DD];
__device__ __half g_attn_l[BB * SS * NQ * DD];
__device__ __half g_q_f[(size_t)BB * NQ * SS * DD];
__device__ __half g_k_f[(size_t)BB * NKV * TT * DD];
__device__ __half g_v_f[(size_t)BB * NKV * TT * DD];

// ---------------------------------------------------------------------------
// Low-level helpers (plain sm_80+ ISA)
// ---------------------------------------------------------------------------
__device__ __forceinline__ uint32_t smem_u32(const void* p) {
    uint32_t a;
    asm("{ .reg .u64 t; cvta.to.shared.u64 t, %1; cvt.u32.u64 %0, t; }"
        : "=r"(a) : "l"(p));
    return a;
}
__device__ __forceinline__ void cp16(uint32_t dst, const void* src) {
    asm volatile("cp.async.cg.shared.global [%0], [%1], 16;"
                 :: "r"(dst), "l"(src));
}
__device__ __forceinline__ void ldsm4(uint32_t* r, uint32_t a) {
    asm volatile("ldmatrix.sync.aligned.m8n8.x4.shared.b16 {%0,%1,%2,%3}, [%4];"
                 : "=r"(r[0]), "=r"(r[1]), "=r"(r[2]), "=r"(r[3]) : "r"(a));
}
__device__ __forceinline__ void ldsm4t(uint32_t* r, uint32_t a) {
    asm volatile("ldmatrix.sync.aligned.m8n8.x4.trans.shared.b16 {%0,%1,%2,%3}, [%4];"
                 : "=r"(r[0]), "=r"(r[1]), "=r"(r[2]), "=r"(r[3]) : "r"(a));
}
__device__ __forceinline__ void mma16816h(float* c, const uint32_t* a,
                                          const uint32_t b0, const uint32_t b1) {
    asm volatile(
        "mma.sync.aligned.m16n8k16.row.col.f32.f16.f16.f32 "
        "{%0,%1,%2,%3}, {%4,%5,%6,%7}, {%8,%9}, {%0,%1,%2,%3};"
        : "+f"(c[0]), "+f"(c[1]), "+f"(c[2]), "+f"(c[3])
        : "r"(a[0]), "r"(a[1]), "r"(a[2]), "r"(a[3]), "r"(b0), "r"(b1));
}

// ---------------------------------------------------------------------------
// fp32 -> fp16 convert (GEMM1 activations)
// ---------------------------------------------------------------------------
__global__ void conv_f16(const float* __restrict__ x,
                         __half* __restrict__ xo, int n)
{
    int i = blockIdx.x * blockDim.x + threadIdx.x;
    if (i >= n) return;
    xo[i] = __float2half(x[i]);
}

// fp32 [R,C] -> fp16 transposed [C,R] (weights)
__global__ void trans_f16(const float* __restrict__ x,
                          __half* __restrict__ xo, int R, int C)
{
    __shared__ float t[32][33];
    int r0 = blockIdx.y * 32, c0 = blockIdx.x * 32;
    int tx = threadIdx.x, ty = threadIdx.y;
#pragma unroll
    for (int j = 0; j < 4; j++)
        t[ty + 8 * j][tx] = x[(size_t)(r0 + ty + 8 * j) * C + c0 + tx];
    __syncthreads();
#pragma unroll
    for (int j = 0; j < 4; j++)
        xo[(size_t)(c0 + ty + 8 * j) * R + r0 + tx] = __float2half(t[tx][ty + 8 * j]);
}

// ---------------------------------------------------------------------------
// fp16 single-pass GEMM (QKV): round-12 champion config.
// ---------------------------------------------------------------------------
#define X1_A_OFF 0
#define X1_B_OFF 16384
#define X1_STAGE 49152
#define GEMM1_SMEM (3 * X1_STAGE)

#define LOAD_STAGE1(c, s) do {                                             \
    int _k0 = (c) * 64;                                                    \
    uint32_t _stb = smb + (s) * X1_STAGE;                                  \
    _Pragma("unroll")                                                      \
    for (int _i = 0; _i < 4; _i++) {                                       \
        int _id = tid + _i * 256;                                          \
        int _row = _id >> 3, _ch = _id & 7;                                \
        uint32_t _sw = (_row << 7) + ((_ch ^ (_row & 7)) << 4);            \
        cp16(_stb + X1_A_OFF + _sw, srcA + (size_t)_row * K + _k0 + _ch * 8); \
    }                                                                      \
    _Pragma("unroll")                                                      \
    for (int _i = 0; _i < 8; _i++) {                                       \
        int _id = tid + _i * 256;                                          \
        int _row = _id >> 3, _ch = _id & 7;                                \
        uint32_t _sw = (_row << 7) + ((_ch ^ (_row & 7)) << 4);            \
        cp16(_stb + X1_B_OFF + _sw, srcB + (size_t)_row * K + _k0 + _ch * 8); \
    }                                                                      \
    asm volatile("cp.async.commit_group;");                                \
} while (0)

__global__ __launch_bounds__(256, 1) void gemm_f16x1(
    const __half* __restrict__ A, const __half* __restrict__ B,
    float* __restrict__ C, int M, int N, int K)
{
    extern __shared__ char sm[];
    const uint32_t smb = smem_u32(sm);
    const int tid = threadIdx.x;
    const int wid = tid >> 5, lane = tid & 31;
    const int bm = blockIdx.y * 128, bn = blockIdx.x * 256;
    const int wm = (wid & 1) * 64, wn = (wid >> 1) * 64;

    const __half* srcA = A + (size_t)bm * K;
    const __half* srcB = B + (size_t)bn * K;

    uint32_t arb[4], brb[4];
    int rswA[4], rswB[4];
#pragma unroll
    for (int mi = 0; mi < 4; mi++) {
        int row = wm + mi * 16 + (lane & 15);
        arb[mi] = (uint32_t)(row << 7) + X1_A_OFF;
        rswA[mi] = row & 7;
    }
#pragma unroll
    for (int ni = 0; ni < 4; ni++) {
        int row = wn + ni * 16 + (lane & 15);
        brb[ni] = (uint32_t)(row << 7) + X1_B_OFF;
        rswB[ni] = row & 7;
    }

    float acc[4][8][4];
#pragma unroll
    for (int i = 0; i < 4; i++)
#pragma unroll
        for (int j = 0; j < 8; j++)
#pragma unroll
            for (int e = 0; e < 4; e++) acc[i][j][e] = 0.f;

    const int NC = K / 64;
    LOAD_STAGE1(0, 0);
    LOAD_STAGE1(1, 1);

    uint32_t ah[2][4][4], bh[2][4][4];
    int sc = 0, sl = 2;
    for (int c = 0; c < NC; c++) {
        __syncthreads();
        if (c + 2 < NC) {
            LOAD_STAGE1(c + 2, sl);
            asm volatile("cp.async.wait_group 2;");
        } else if (c + 1 < NC) {
            asm volatile("cp.async.wait_group 1;");
        } else {
            asm volatile("cp.async.wait_group 0;");
        }
        __syncthreads();

        const uint32_t base = smb + sc * X1_STAGE;
        {
            const int c0 = (lane >> 4);
#pragma unroll
            for (int mi = 0; mi < 4; mi++)
                ldsm4(ah[0][mi], base + arb[mi] + ((c0 ^ rswA[mi]) << 4));
#pragma unroll
            for (int ni = 0; ni < 4; ni++)
                ldsm4(bh[0][ni], base + brb[ni] + ((c0 ^ rswB[ni]) << 4));
        }
#pragma unroll
        for (int ks = 0; ks < 4; ks++) {
            const int cur = ks & 1, nxt = cur ^ 1;
            if (ks < 3) {
                const int c0 = (ks + 1) * 2 + (lane >> 4);
#pragma unroll
                for (int mi = 0; mi < 4; mi++)
                    ldsm4(ah[nxt][mi], base + arb[mi] + ((c0 ^ rswA[mi]) << 4));
#pragma unroll
                for (int ni = 0; ni < 4; ni++)
                    ldsm4(bh[nxt][ni], base + brb[ni] + ((c0 ^ rswB[ni]) << 4));
            }
#pragma unroll
            for (int mi = 0; mi < 4; mi++)
#pragma unroll
                for (int ni = 0; ni < 4; ni++)
#pragma unroll
                    for (int sel = 0; sel < 2; sel++)
                        mma16816h(acc[mi][ni * 2 + sel], ah[cur][mi],
                                  bh[cur][ni][sel], bh[cur][ni][sel + 2]);
        }
        sc = (sc == 2) ? 0 : sc + 1;
        sl = (sl == 2) ? 0 : sl + 1;
    }

    const int g = lane >> 2, t = lane & 3;
#pragma unroll
    for (int mi = 0; mi < 4; mi++) {
#pragma unroll
        for (int nj = 0; nj < 8; nj++) {
            const float* a = acc[mi][nj];
            int row = bm + wm + mi * 16 + g;
            int col = bn + wn + nj * 8 + t * 2;
            *(float2*)&C[(size_t)row * N + col] = make_float2(a[0], a[1]);
            *(float2*)&C[(size_t)(row + 8) * N + col] = make_float2(a[2], a[3]);
        }
    }
}

// ---------------------------------------------------------------------------
// fp16x2 GEMM (output projection) — round-12 version, unchanged.
// ---------------------------------------------------------------------------
#define AH_OFF 0
#define AL_OFF 16384
#define BH_OFF 32768
#define STAGE_B  65536
#define GEMM_SMEM (3 * STAGE_B)

#define LOAD_STAGE(c, s) do {                                              \
    int _k0 = (c) * 64;                                                    \
    uint32_t _stb = smb + (s) * STAGE_B;                                   \
    _Pragma("unroll")                                                      \
    for (int _i = 0; _i < 4; _i++) {                                       \
        int _id = tid + _i * 256;                                          \
        int _row = _id >> 3, _ch = _id & 7;                                \
        uint32_t _sw = (_row << 7) + ((_ch ^ (_row & 7)) << 4);            \
        const size_t _go = (size_t)_row * K + _k0 + _ch * 8;               \
        cp16(_stb + AH_OFF + _sw, srcAh + _go);                            \
        cp16(_stb + AL_OFF + _sw, srcAl + _go);                            \
    }                                                                      \
    _Pragma("unroll")                                                      \
    for (int _i = 0; _i < 8; _i++) {                                       \
        int _id = tid + _i * 256;                                          \
        int _row = _id >> 3, _ch = _id & 7;                                \
        uint32_t _sw = (_row << 7) + ((_ch ^ (_row & 7)) << 4);            \
        cp16(_stb + BH_OFF + _sw, srcB + (size_t)_row * K + _k0 + _ch * 8); \
    }                                                                      \
    asm volatile("cp.async.commit_group;");                                \
} while (0)

__global__ __launch_bounds__(256, 1) void gemm_f16x2(
    const __half* __restrict__ Ah, const __half* __restrict__ Al,
    const __half* __restrict__ B,
    float* __restrict__ C, int M, int N, int K)
{
    extern __shared__ char sm[];
    const uint32_t smb = smem_u32(sm);
    const int tid = threadIdx.x;
    const int wid = tid >> 5, lane = tid & 31;
    const int bm = blockIdx.y * 128, bn = blockIdx.x * 256;
    const int wm = (wid & 1) * 64, wn = (wid >> 1) * 64;

    const __half* srcAh = Ah + (size_t)bm * K;
    const __half* srcAl = Al + (size_t)bm * K;
    const __half* srcB  = B  + (size_t)bn * K;

    uint32_t arb[4], brb[4];
    int rswA[4], rswB[4];
#pragma unroll
    for (int mi = 0; mi < 4; mi++) {
        int row = wm + mi * 16 + (lane & 15);
        arb[mi] = (uint32_t)(row << 7);
        rswA[mi] = row & 7;
    }
#pragma unroll
    for (int ni = 0; ni < 4; ni++) {
        int row = wn + ni * 16 + (lane & 15);
        brb[ni] = (uint32_t)(row << 7);
        rswB[ni] = row & 7;
    }

    float acc[4][8][4];
#pragma unroll
    for (int i = 0; i < 4; i++)
#pragma unroll
        for (int j = 0; j < 8; j++)
#pragma unroll
            for (int e = 0; e < 4; e++) acc[i][j][e] = 0.f;

    const int NC = K / 64;
    LOAD_STAGE(0, 0);
    LOAD_STAGE(1, 1);

    uint32_t ah[2][4][4], bh[2][4][4], al[4][4];
    int sc = 0, sl = 2;
    for (int c = 0; c < NC; c++) {
        __syncthreads();
        if (c + 2 < NC) {
            LOAD_STAGE(c + 2, sl);
            asm volatile("cp.async.wait_group 2;");
        } else if (c + 1 < NC) {
            asm volatile("cp.async.wait_group 1;");
        } else {
            asm volatile("cp.async.wait_group 0;");
        }
        __syncthreads();

        const uint32_t base = smb + sc * STAGE_B;
        {
            const int c0 = (lane >> 4);
#pragma unroll
            for (int mi = 0; mi < 4; mi++)
                ldsm4(ah[0][mi], base + AH_OFF + arb[mi] + ((c0 ^ rswA[mi]) << 4));
#pragma unroll
            for (int ni = 0; ni < 4; ni++)
                ldsm4(bh[0][ni], base + BH_OFF + brb[ni] + ((c0 ^ rswB[ni]) << 4));
        }
#pragma unroll
        for (int ks = 0; ks < 4; ks++) {
            const int cur = ks & 1, nxt = cur ^ 1;
            const int c0c = ks * 2 + (lane >> 4);
#pragma unroll
            for (int mi = 0; mi < 4; mi++)
                ldsm4(al[mi], base + AL_OFF + arb[mi] + ((c0c ^ rswA[mi]) << 4));
            if (ks < 3) {
                const int c0n = (ks + 1) * 2 + (lane >> 4);
#pragma unroll
                for (int mi = 0; mi < 4; mi++)
                    ldsm4(ah[nxt][mi], base + AH_OFF + arb[mi] + ((c0n ^ rswA[mi]) << 4));
#pragma unroll
                for (int ni = 0; ni < 4; ni++)
                    ldsm4(bh[nxt][ni], base + BH_OFF + brb[ni] + ((c0n ^ rswB[ni]) << 4));
            }
#pragma unroll
            for (int mi = 0; mi < 4; mi++)
#pragma unroll
                for (int ni = 0; ni < 4; ni++)
#pragma unroll
                    for (int sel = 0; sel < 2; sel++)
                        mma16816h(acc[mi][ni * 2 + sel], ah[cur][mi],
                                  bh[cur][ni][sel], bh[cur][ni][sel + 2]);
#pragma unroll
            for (int mi = 0; mi < 4; mi++)
#pragma unroll
                for (int ni = 0; ni < 4; ni++)
#pragma unroll
                    for (int sel = 0; sel < 2; sel++)
                        mma16816h(acc[mi][ni * 2 + sel], al[mi],
                                  bh[cur][ni][sel], bh[cur][ni][sel + 2]);
        }
        sc = (sc == 2) ? 0 : sc + 1;
        sl = (sl == 2) ? 0 : sl + 1;
    }

    const int g = lane >> 2, t = lane & 3;
#pragma unroll
    for (int mi = 0; mi < 4; mi++) {
#pragma unroll
        for (int nj = 0; nj < 8; nj++) {
            const float* a = acc[mi][nj];
            int row = bm + wm + mi * 16 + g;
            int col = bn + wn + nj * 8 + t * 2;
            *(float2*)&C[(size_t)row * N + col] = make_float2(a[0], a[1]);
            *(float2*)&C[(size_t)(row + 8) * N + col] = make_float2(a[2], a[3]);
        }
    }
}

// ---------------------------------------------------------------------------
// Fused pre-pass (round-12 version)
// ---------------------------------------------------------------------------
#define NQTOT (BB * SS * NQ * 64)
#define KVTOT (BB * NKV * TT * 64)

__global__ void prep_qkv_f16(const float* __restrict__ qkv,
                             const float* __restrict__ kcache,
                             const float* __restrict__ vcache,
                             const float* __restrict__ cosb,
                             const float* __restrict__ sinb,
                             __half* __restrict__ qf,
                             __half* __restrict__ kf, __half* __restrict__ vf)
{
    int idx = blockIdx.x * blockDim.x + threadIdx.x;
    if (idx < NQTOT) {
        int d = idx & 63;
        int rest = idx >> 6;
        int h = rest % NQ;
        int s = (rest / NQ) % SS;
        int b = rest / (NQ * SS);
        const float* base = &qkv[((size_t)(b * SS + s)) * QKVN + h * DD];
        float x1 = base[d], x2 = base[d + 64];
        float c0 = cosb[s * DD + d],      s0 = sinb[s * DD + d];
        float c1 = cosb[s * DD + d + 64], s1 = sinb[s * DD + d + 64];
        size_t o = (((size_t)(b * NQ + h)) * SS + s) * DD + d;
        qf[o]      = __float2half((x1 * c0 - x2 * s0) * SCALE);
        qf[o + 64] = __float2half((x2 * c1 + x1 * s1) * SCALE);
        return;
    }
    idx -= NQTOT;
    if (idx >= KVTOT) return;
    int d = idx & 63;
    int rest = idx >> 6;
    int t = rest % TT;
    int kh = (rest / TT) % NKV;
    int b = rest / (TT * NKV);

    float k1, k2, v1, v2;
    if (t < PP) {
        size_t src = (((size_t)(b * PP + t)) * NKV + kh) * DD;
        k1 = kcache[src + d]; k2 = kcache[src + d + 64];
        v1 = vcache[src + d]; v2 = vcache[src + d + 64];
    } else {
        int s = t - PP;
        const float* base = &qkv[((size_t)(b * SS + s)) * QKVN];
        float x1 = base[(NQ + kh) * DD + d], x2 = base[(NQ + kh) * DD + d + 64];
        float c0 = cosb[s * DD + d],      s0 = sinb[s * DD + d];
        float c1 = cosb[s * DD + d + 64], s1 = sinb[s * DD + d + 64];
        k1 = x1 * c0 - x2 * s0;
        k2 = x2 * c1 + x1 * s1;
        v1 = base[(NQ + NKV + kh) * DD + d];
        v2 = base[(NQ + NKV + kh) * DD + d + 64];
    }
    size_t o = (((size_t)(b * NKV + kh)) * TT + t) * DD + d;
    kf[o]      = __float2half(k1);
    kf[o + 64] = __float2half(k2);
    vf[o]      = __float2half(v1);
    vf[o + 64] = __float2half(v2);
}

// ---------------------------------------------------------------------------
// Flash attention — round-12 version + batch-offset parameter.
// ---------------------------------------------------------------------------
#define FA_SMEM (2 * 64 * 256)

__global__ __launch_bounds__(128) void flash_mma(
    const __half* __restrict__ qf_g,
    const __half* __restrict__ kf_g,
    const __half* __restrict__ vf_g,
    __half* __restrict__ attnh, __half* __restrict__ attnl, int bbase)
{
    extern __shared__ char sm[];
    const uint32_t smb = smem_u32(sm);
    const uint32_t KO = 0, VO = 16384;
    const int tid = threadIdx.x, lane = tid & 31, w = tid >> 5;
    const int qi = blockIdx.x, h = blockIdx.y;
    const int b = bbase;
    const int sq0 = qi * 64;
    const int khd = h >> 2;
    const int g = lane >> 2, t4 = lane & 3;
    const int r0 = w * 16 + g, r1 = r0 + 8;

    uint32_t qf[8][4];
    {
        const __half* qb = qf_g + (((size_t)(b * NQ + h)) * SS + sq0) * DD;
#pragma unroll
        for (int ks = 0; ks < 8; ks++) {
            int c0 = ks * 16 + 2 * t4;
            qf[ks][0] = *(const uint32_t*)(qb + r0 * DD + c0);
            qf[ks][1] = *(const uint32_t*)(qb + r1 * DD + c0);
            qf[ks][2] = *(const uint32_t*)(qb + r0 * DD + c0 + 8);
            qf[ks][3] = *(const uint32_t*)(qb + r1 * DD + c0 + 8);
        }
    }

    uint32_t krb[4];
    int krsw[4];
#pragma unroll
    for (int kg = 0; kg < 4; kg++) {
        int r = kg * 16 + (lane & 15);
        krb[kg] = (uint32_t)(r * 256);
        krsw[kg] = r & 7;
    }

    float oacc[16][4];
#pragma unroll
    for (int i = 0; i < 16; i++)
#pragma unroll
        for (int j = 0; j < 4; j++) oacc[i][j] = 0.f;
    float m0 = -1e30f, m1 = -1e30f, l0 = 0.f, l1 = 0.f;

    const size_t kvb = ((size_t)(b * NKV + khd)) * TT * DD;
    const int nt = qi + 1 + PP / 64;

    for (int kt = 0; kt < nt; kt++) {
        __syncthreads();
        {
            const __half* srcK = kf_g + kvb + (size_t)kt * 64 * DD;
            const __half* srcV = vf_g + kvb + (size_t)kt * 64 * DD;
#pragma unroll
            for (int i = 0; i < 8; i++) {
                int id = tid + i * 128;
                int r = id >> 4, ch = id & 15;
                uint32_t sw = r * 256 + ((ch ^ (r & 7)) << 4);
                cp16(smb + KO + sw, srcK + r * DD + ch * 8);
                cp16(smb + VO + sw, srcV + r * DD + ch * 8);
            }
            asm volatile("cp.async.commit_group;");
            asm volatile("cp.async.wait_group 0;");
            __syncthreads();
        }

        float sacc[8][4];
#pragma unroll
        for (int j = 0; j < 8; j++)
#pragma unroll
            for (int e = 0; e < 4; e++) sacc[j][e] = 0.f;

        uint32_t kb[2][4][4];
        {
            const int c0 = (lane >> 4);
#pragma unroll
            for (int kg = 0; kg < 4; kg++)
                ldsm4(kb[0][kg], smb + KO + krb[kg] + ((c0 ^ krsw[kg]) << 4));
        }
#pragma unroll
        for (int ks = 0; ks < 8; ks++) {
            const int cur = ks & 1, nxt = cur ^ 1;
            if (ks < 7) {
                const int c0 = (ks + 1) * 2 + (lane >> 4);
#pragma unroll
                for (int kg = 0; kg < 4; kg++)
                    ldsm4(kb[nxt][kg], smb + KO + krb[kg] + ((c0 ^ krsw[kg]) << 4));
            }
#pragma unroll
            for (int kg = 0; kg < 4; kg++)
#pragma unroll
                for (int sel = 0; sel < 2; sel++)
                    mma16816h(sacc[kg * 2 + sel], qf[ks],
                              kb[cur][kg][sel], kb[cur][kg][sel + 2]);
        }

        if (kt == nt - 1) {
#pragma unroll
            for (int j = 0; j < 8; j++) {
                int cb = j * 8 + 2 * t4;
                if (cb     > r0) sacc[j][0] = -1e30f;
                if (cb + 1 > r0) sacc[j][1] = -1e30f;
                if (cb     > r1) sacc[j][2] = -1e30f;
                if (cb + 1 > r1) sacc[j][3] = -1e30f;
            }
        }

        float mx0 = m0, mx1 = m1;
#pragma unroll
        for (int j = 0; j < 8; j++) {
            mx0 = fmaxf(mx0, fmaxf(sacc[j][0], sacc[j][1]));
            mx1 = fmaxf(mx1, fmaxf(sacc[j][2], sacc[j][3]));
        }
        mx0 = fmaxf(mx0, __shfl_xor_sync(0xffffffff, mx0, 1));
        mx0 = fmaxf(mx0, __shfl_xor_sync(0xffffffff, mx0, 2));
        mx1 = fmaxf(mx1, __shfl_xor_sync(0xffffffff, mx1, 1));
        mx1 = fmaxf(mx1, __shfl_xor_sync(0xffffffff, mx1, 2));
        float rs0 = __expf(m0 - mx0), rs1 = __expf(m1 - mx1);
        m0 = mx0; m1 = mx1;
        l0 *= rs0; l1 *= rs1;

        uint32_t pf[4][4];
#pragma unroll
        for (int j = 0; j < 8; j++) {
            float p0 = __expf(sacc[j][0] - m0);
            float p1 = __expf(sacc[j][1] - m0);
            float p2 = __expf(sacc[j][2] - m1);
            float p3 = __expf(sacc[j][3] - m1);
            l0 += p0 + p1; l1 += p2 + p3;
            int kk = j >> 1, u = (j & 1) * 2;
            __half2 hA = __float22half2_rn(make_float2(p0, p1));
            __half2 hB = __float22half2_rn(make_float2(p2, p3));
            pf[kk][u]     = *(uint32_t*)&hA;
            pf[kk][u + 1] = *(uint32_t*)&hB;
        }

#pragma unroll
        for (int i = 0; i < 16; i++) {
            oacc[i][0] *= rs0; oacc[i][1] *= rs0;
            oacc[i][2] *= rs1; oacc[i][3] *= rs1;
        }

        uint32_t vfr[2][2][4];
        {
            int r = (lane & 15);
            int cA = (lane >> 4);
            int cB = 2 + (lane >> 4);
            ldsm4t(vfr[0][0], smb + VO + r * 256 + ((cA ^ (r & 7)) << 4));
            ldsm4t(vfr[0][1], smb + VO + r * 256 + ((cB ^ (r & 7)) << 4));
        }
#pragma unroll
        for (int idx = 0; idx < 16; idx++) {
            const int cur = idx & 1, nxt = cur ^ 1;
            const int kk = idx >> 2, dp = idx & 3;
            if (idx < 15) {
                const int kk2 = (idx + 1) >> 2, dp2 = (idx + 1) & 3;
                int r = kk2 * 16 + (lane & 15);
                int cA = dp2 * 4 + (lane >> 4);
                int cB = dp2 * 4 + 2 + (lane >> 4);
                ldsm4t(vfr[nxt][0], smb + VO + r * 256 + ((cA ^ (r & 7)) << 4));
                ldsm4t(vfr[nxt][1], smb + VO + r * 256 + ((cB ^ (r & 7)) << 4));
            }
            const int dg0 = dp * 2, dg1 = dp * 2 + 1;
            mma16816h(oacc[dg0 * 2],     pf[kk], vfr[cur][0][0], vfr[cur][0][1]);
            mma16816h(oacc[dg0 * 2 + 1], pf[kk], vfr[cur][0][2], vfr[cur][0][3]);
            mma16816h(oacc[dg1 * 2],     pf[kk], vfr[cur][1][0], vfr[cur][1][1]);
            mma16816h(oacc[dg1 * 2 + 1], pf[kk], vfr[cur][1][2], vfr[cur][1][3]);
        }
    }

    l0 += __shfl_xor_sync(0xffffffff, l0, 1);
    l0 += __shfl_xor_sync(0xffffffff, l0, 2);
    l1 += __shfl_xor_sync(0xffffffff, l1, 1);
    l1 += __shfl_xor_sync(0xffffffff, l1, 2);
    float inv0 = 1.f / l0, inv1 = 1.f / l1;

    size_t rowA = ((size_t)(b * SS + sq0 + r0)) * (NQ * DD) + h * DD;
    size_t rowB = ((size_t)(b * SS + sq0 + r1)) * (NQ * DD) + h * DD;
#pragma unroll
    for (int dt = 0; dt < 16; dt++) {
        int c = dt * 8 + 2 * t4;
        float v0 = oacc[dt][0] * inv0, v1 = oacc[dt][1] * inv0;
        float v2 = oacc[dt][2] * inv1, v3 = oacc[dt][3] * inv1;
        __half2 hA = __float22half2_rn(make_float2(v0, v1));
        float2 fA = __half22float2(hA);
        __half2 lA = __float22half2_rn(make_float2(v0 - fA.x, v1 - fA.y));
        __half2 hB = __float22half2_rn(make_float2(v2, v3));
        float2 fB = __half22float2(hB);
        __half2 lB = __float22half2_rn(make_float2(v2 - fB.x, v3 - fB.y));
        *(__half2*)&attnh[rowA + c] = hA;
        *(__half2*)&attnl[rowA + c] = lA;
        *(__half2*)&attnh[rowB + c] = hB;
        *(__half2*)&attnl[rowB + c] = lB;
    }
}

// ---------------------------------------------------------------------------
extern "C" void kernel_launch(void* const* d_in, const int* in_sizes, int n_in,
                              void* d_out, int out_size)
{
    const float* hidden = (const float*)d_in[0];
    const float* w_qkv  = (const float*)d_in[1];
    const float* w_o    = (const float*)d_in[2];
    const float* cosb   = (const float*)d_in[3];
    const float* sinb   = (const float*)d_in[4];
    const float* kc     = (const float*)d_in[5];
    const float* vc     = (const float*)d_in[6];
    float* out = (float*)d_out;

    float *qkv;
    __half *hidf, *wq, *wo, *ath, *atl, *qf, *kf, *vf;
    cudaGetSymbolAddress((void**)&qkv, g_qkv);
    cudaGetSymbolAddress((void**)&hidf, g_hid);
    cudaGetSymbolAddress((void**)&wq, g_wqkv);
    cudaGetSymbolAddress((void**)&wo, g_wo);
    cudaGetSymbolAddress((void**)&ath, g_attn_h);
    cudaGetSymbolAddress((void**)&atl, g_attn_l);
    cudaGetSymbolAddress((void**)&qf, g_q_f);
    cudaGetSymbolAddress((void**)&kf, g_k_f);
    cudaGetSymbolAddress((void**)&vf, g_v_f);

    cudaFuncSetAttribute(gemm_f16x1,
                         cudaFuncAttributeMaxDynamicSharedMemorySize, GEMM1_SMEM);
    cudaFuncSetAttribute(gemm_f16x2,
                         cudaFuncAttributeMaxDynamicSharedMemorySize, GEMM_SMEM);
    cudaFuncSetAttribute(flash_mma,
                         cudaFuncAttributeMaxDynamicSharedMemorySize, FA_SMEM);

    const int M = BB * SS;  // 2048

    // second stream + fork/join events (all graph-capturable)
    cudaStream_t s2;
    cudaStreamCreateWithFlags(&s2, cudaStreamNonBlocking);
    cudaEvent_t evRoot, evWo, evPrep, evSide;
    cudaEventCreateWithFlags(&evRoot, cudaEventDisableTiming);
    cudaEventCreateWithFlags(&evWo,   cudaEventDisableTiming);
    cudaEventCreateWithFlags(&evPrep, cudaEventDisableTiming);
    cudaEventCreateWithFlags(&evSide, cudaEventDisableTiming);

    // fork: trans_wo runs on s2 concurrently with the main chain
    cudaEventRecord(evRoot, 0);
    cudaStreamWaitEvent(s2, evRoot, 0);
    trans_f16<<<dim3(HH / 32, HH / 32), dim3(32, 8), 0, s2>>>(w_o, wo, HH, HH);
    cudaEventRecord(evWo, s2);

    // main chain: conv + trans_wqkv -> GEMM1 -> prep
    {
        int n = M * HH;
        conv_f16<<<(n + 255) / 256, 256>>>(hidden, hidf, n);
        trans_f16<<<dim3(QKVN / 32, HH / 32), dim3(32, 8)>>>(w_qkv, wq, HH, QKVN);
    }
    gemm_f16x1<<<dim3(QKVN / 256, M / 128), 256, GEMM1_SMEM>>>(
        hidf, wq, qkv, M, QKVN, HH);
    {
        int total = NQTOT + KVTOT;
        prep_qkv_f16<<<(total + 255) / 256, 256>>>(qkv, kc, vc, cosb, sinb,
                                                   qf, kf, vf);
    }
    cudaEventRecord(evPrep, 0);

    // side chain (s2): flash(b=1) -> GEMM2(rows 1024..2047)
    cudaStreamWaitEvent(s2, evPrep, 0);
    flash_mma<<<dim3(SS / 64, NQ, 1), 128, FA_SMEM, s2>>>(
        qf, kf, vf, ath, atl, 1);
    gemm_f16x2<<<dim3(HH / 256, SS / 128), 256, GEMM_SMEM, s2>>>(
        ath + (size_t)SS * NQ * DD, atl + (size_t)SS * NQ * DD, wo,
        out + (size_t)SS * HH, SS, HH, HH);
    cudaEventRecord(evSide, s2);

    // main chain: flash(b=0) -> GEMM2(rows 0..1023)
    flash_mma<<<dim3(SS / 64, NQ, 1), 128, FA_SMEM>>>(qf, kf, vf, ath, atl, 0);
    cudaStreamWaitEvent(0, evWo, 0);
    gemm_f16x2<<<dim3(HH / 256, SS / 128), 256, GEMM_SMEM>>>(
        ath, atl, wo, out, SS, HH, HH);

    // join side chain into origin
    cudaStreamWaitEvent(0, evSide, 0);

    // cleanup — only when not inside graph capture (destroying capturing
    // resources would invalidate the capture)
    cudaStreamCaptureStatus st = cudaStreamCaptureStatusNone;
    cudaStreamIsCapturing(s2, &st);
    if (st == cudaStreamCaptureStatusNone) {
        cudaStreamDestroy(s2);
        cudaEventDestroy(evRoot);
        cudaEventDestroy(evWo);
        cudaEventDestroy(evPrep);
        cudaEventDestroy(evSide);
    }
}